// round 16
// baseline (speedup 1.0000x reference)
#include <cuda_runtime.h>
#include <cuda_fp16.h>
#include <cstdint>

#define LN_EPS 1e-5f

static constexpr int Fdim = 64;
static constexpr int Hdim = 128;
static constexpr int SLABP = 130;                    // word pitch (even -> int2-aligned)
static constexpr int SLAB_BYTES = 128 * SLABP * 4;   // 66560: [16 warpsweeps x 8 q][128 cols]

// cross-CTA combine scratch (written every launch before read; counter self-resets)
__device__ int d_partial[1024][128];
__device__ int d_counter[512];

// pack two floats as fp16x2: lo -> low half, hi -> high half
__device__ __forceinline__ uint32_t packh(float lo, float hi) {
    uint32_t r;
    asm("cvt.rn.f16x2.f32 %0, %1, %2;" : "=r"(r) : "f"(hi), "f"(lo));
    return r;
}

__device__ __forceinline__ void mma_f16(float c[4], const uint32_t a[4], const uint32_t b[2]) {
    asm volatile(
        "mma.sync.aligned.m16n8k16.row.col.f32.f16.f16.f32 "
        "{%0,%1,%2,%3}, {%4,%5,%6,%7}, {%8,%9}, {%0,%1,%2,%3};\n"
        : "+f"(c[0]), "+f"(c[1]), "+f"(c[2]), "+f"(c[3])
        : "r"(a[0]), "r"(a[1]), "r"(a[2]), "r"(a[3]), "r"(b[0]), "r"(b[1]));
}

// grid = 2N: CTA (n, half) owns 256 rows; 8 warps x 16 rows x 2 sweeps.
// fp16 GEMM (bias in acc init) -> LN -> ReLU -> y. Pool: plain STS.64 into a
// private (warpsweep, q) slab row — ZERO mainloop atomics — then a register
// fold. Cross-CTA combine via d_partial; last arriver writes g + broadcast.
extern "C" __global__ void __launch_bounds__(256, 2)
fused_kernel(const float* __restrict__ x, const int* __restrict__ mask,
             const float* __restrict__ W, const float* __restrict__ bias,
             const float* __restrict__ gamma, const float* __restrict__ beta,
             float* __restrict__ out, float* __restrict__ gout, int L)
{
    extern __shared__ int slab[];           // [128][SLABP] pooled values (float bits >= 0)
    __shared__ uint4  Bfrag[4 * 8 * 32];    // [ks][tpair][lane] = {t0.x,t0.y,t1.x,t1.y}
    __shared__ int    gsm[128];
    __shared__ float4 cgb[16][4];           // {g0, g1, b0, b1} per (t, s)
    __shared__ float2 cb[16][4];            // bias pair per (t, s)
    __shared__ int    sIsLast;

    const int tid  = threadIdx.x;
    const int bidx = blockIdx.x;
    const int n    = bidx >> 1;
    const int half = bidx & 1;

    // pack W into paired fp16 mma B-fragment order
    for (int idx = tid; idx < 4 * 8 * 32; idx += 256) {
        int lane = idx & 31;
        int tp   = (idx >> 5) & 7;
        int ks   = idx >> 8;
        int q = lane >> 2, s = lane & 3;
        int f0 = ks * 16 + s * 2;
        int h0 = (2 * tp) * 8 + q;
        int h1 = (2 * tp + 1) * 8 + q;
        float2 a01 = *reinterpret_cast<const float2*>(W + h0 * Fdim + f0);
        float2 a89 = *reinterpret_cast<const float2*>(W + h0 * Fdim + f0 + 8);
        float2 b01 = *reinterpret_cast<const float2*>(W + h1 * Fdim + f0);
        float2 b89 = *reinterpret_cast<const float2*>(W + h1 * Fdim + f0 + 8);
        uint4 v;
        v.x = packh(a01.x, a01.y);
        v.y = packh(a89.x, a89.y);
        v.z = packh(b01.x, b01.y);
        v.w = packh(b89.x, b89.y);
        Bfrag[idx] = v;
    }
    // stage gamma/beta/bias (64 (t,s) pairs)
    if (tid < 64) {
        int t = tid >> 2, s = tid & 3;
        int col = t * 8 + 2 * s;
        float2 g2 = *reinterpret_cast<const float2*>(gamma + col);
        float2 b2 = *reinterpret_cast<const float2*>(beta  + col);
        cgb[t][s] = make_float4(g2.x, g2.y, b2.x, b2.y);
        cb[t][s]  = *reinterpret_cast<const float2*>(bias + col);
    }
    __syncthreads();   // slab needs no init: every row is fully overwritten below

    const int lane = tid & 31;
    const int warp = tid >> 5;
    const int q = lane >> 2, s = lane & 3;

    const int rbeg = half * 256;
    int sw = 0;
    for (int rb = rbeg + warp * 16; rb < rbeg + 256; rb += 128, sw++) {
        const size_t rowA = (size_t)n * L + rb + q;
        const size_t rowB = rowA + 8;
        const float* xA = x + rowA * Fdim;
        const float* xB = x + rowB * Fdim;
        int* prow = slab + ((sw * 8 + warp) * 8 + q) * SLABP;   // private pool row

        // acc initialized with bias (folds the post-GEMM bias add into init)
        float acc[16][4];
        #pragma unroll
        for (int t = 0; t < 16; t++) {
            float2 bb = cb[t][s];
            acc[t][0] = bb.x; acc[t][1] = bb.y;
            acc[t][2] = bb.x; acc[t][3] = bb.y;
        }

        #pragma unroll
        for (int ks = 0; ks < 4; ks++) {
            const int f0 = ks * 16 + s * 2;
            float2 A0 = *reinterpret_cast<const float2*>(xA + f0);
            float2 A8 = *reinterpret_cast<const float2*>(xA + f0 + 8);
            float2 B0 = *reinterpret_cast<const float2*>(xB + f0);
            float2 B8 = *reinterpret_cast<const float2*>(xB + f0 + 8);
            uint32_t ah[4] = { packh(A0.x, A0.y), packh(B0.x, B0.y),
                               packh(A8.x, A8.y), packh(B8.x, B8.y) };
            const uint4* Bp = Bfrag + ks * 256 + lane;
            #pragma unroll
            for (int tp = 0; tp < 8; tp++) {
                uint4 bv = Bp[tp * 32];
                uint32_t bh0[2] = { bv.x, bv.y };
                uint32_t bh1[2] = { bv.z, bv.w };
                mma_f16(acc[2 * tp],     ah, bh0);
                mma_f16(acc[2 * tp + 1], ah, bh1);
            }
        }

        float sumA = 0.f, sqA = 0.f, sumB = 0.f, sqB = 0.f;
        #pragma unroll
        for (int t = 0; t < 16; t++) {
            sumA += acc[t][0] + acc[t][1];
            sqA  += acc[t][0] * acc[t][0] + acc[t][1] * acc[t][1];
            sumB += acc[t][2] + acc[t][3];
            sqB  += acc[t][2] * acc[t][2] + acc[t][3] * acc[t][3];
        }
        #pragma unroll
        for (int m = 1; m <= 2; m <<= 1) {
            sumA += __shfl_xor_sync(0xffffffffu, sumA, m);
            sqA  += __shfl_xor_sync(0xffffffffu, sqA, m);
            sumB += __shfl_xor_sync(0xffffffffu, sumB, m);
            sqB  += __shfl_xor_sync(0xffffffffu, sqB, m);
        }
        const float inv = 1.0f / (float)Hdim;
        float muA = sumA * inv, muB = sumB * inv;
        float rsA = rsqrtf(fmaxf(sqA * inv - muA * muA, 0.f) + LN_EPS);
        float rsB = rsqrtf(fmaxf(sqB * inv - muB * muB, 0.f) + LN_EPS);

        const bool mA = (mask[rowA] != 0);
        const bool mB = (mask[rowB] != 0);
        float* outA = out + rowA * (2 * Hdim);
        float* outB = out + rowB * (2 * Hdim);

        #pragma unroll
        for (int t = 0; t < 16; t++) {
            int col = t * 8 + 2 * s;
            float4 gb = cgb[t][s];
            float yA0 = fmaxf((acc[t][0] - muA) * rsA * gb.x + gb.z, 0.f);
            float yA1 = fmaxf((acc[t][1] - muA) * rsA * gb.y + gb.w, 0.f);
            float yB0 = fmaxf((acc[t][2] - muB) * rsB * gb.x + gb.z, 0.f);
            float yB1 = fmaxf((acc[t][3] - muB) * rsB * gb.y + gb.w, 0.f);
            *reinterpret_cast<float2*>(outA + col) = make_float2(yA0, yA1);
            *reinterpret_cast<float2*>(outB + col) = make_float2(yB0, yB1);
            // pooled pair -> private slab row: plain STS.64, no atomics
            float p0 = fmaxf(mA ? yA0 : 0.f, mB ? yB0 : 0.f);
            float p1 = fmaxf(mA ? yA1 : 0.f, mB ? yB1 : 0.f);
            *reinterpret_cast<int2*>(prow + col) =
                make_int2(__float_as_int(p0), __float_as_int(p1));
        }
    }
    __syncthreads();

    // fold 128 slab rows -> gsm (each thread: one column over 64 rows, in regs)
    {
        const int col = tid & 127;
        const int hf  = tid >> 7;
        const int* sr = slab + hf * 64 * SLABP + col;
        int m = sr[0];
        #pragma unroll
        for (int r = 1; r < 64; r++) m = max(m, sr[r * SLABP]);
        if (hf == 0) gsm[col] = m;
        __syncthreads();
        if (hf == 1) atomicMax(&gsm[col], m);
    }
    __syncthreads();

    // publish per-CTA partial; last arriver of the pair finishes the batch
    if (tid < 128) d_partial[bidx][tid] = gsm[tid];
    __threadfence();
    __syncthreads();
    if (tid == 0) sIsLast = (atomicAdd(&d_counter[n], 1) == 1);
    __syncthreads();
    if (!sIsLast) return;

    __threadfence();
    if (tid < 128) {
        const int base = n << 1;
        int c = max(d_partial[base][tid], d_partial[base + 1][tid]);
        gsm[tid] = c;
        gout[(size_t)n * Hdim + tid] = __int_as_float(c);
    }
    if (tid == 0) d_counter[n] = 0;   // self-reset for next graph replay
    __syncthreads();

    // broadcast g into out[n, :, H:2H] (whole batch, 8 warps)
    const int lane2 = tid & 31, warp2 = tid >> 5;
    float4 gv;
    gv.x = __int_as_float(gsm[lane2 * 4 + 0]);
    gv.y = __int_as_float(gsm[lane2 * 4 + 1]);
    gv.z = __int_as_float(gsm[lane2 * 4 + 2]);
    gv.w = __int_as_float(gsm[lane2 * 4 + 3]);
    float* obase = out + (size_t)n * L * (2 * Hdim) + Hdim;
    for (int r = warp2; r < L; r += 8)
        *reinterpret_cast<float4*>(obase + (size_t)r * (2 * Hdim) + lane2 * 4) = gv;
}

extern "C" void kernel_launch(void* const* d_in, const int* in_sizes, int n_in,
                              void* d_out, int out_size) {
    const float* x     = (const float*)d_in[0];
    const int*   mask  = (const int*)d_in[1];
    const float* W     = (const float*)d_in[2];
    const float* bias  = (const float*)d_in[3];
    const float* gamma = (const float*)d_in[4];
    const float* beta  = (const float*)d_in[5];
    float* out = (float*)d_out;

    const int NL = in_sizes[1];
    const long long ysize = (long long)NL * 2 * Hdim;
    const int N = (int)(((long long)out_size - ysize) / Hdim);
    const int L = NL / N;
    float* g = out + ysize;

    cudaFuncSetAttribute(fused_kernel, cudaFuncAttributeMaxDynamicSharedMemorySize, SLAB_BYTES);
    fused_kernel<<<2 * N, 256, SLAB_BYTES>>>(x, mask, W, bias, gamma, beta, out, g, L);
}